// round 2
// baseline (speedup 1.0000x reference)
#include <cuda_runtime.h>
#include <cstdint>

// Problem constants: B=2, S=2048, H=1024, NH=16, D=64; M = B*S = 4096

static __device__ float g_qkv[4096 * 3072];   // qkv projection scratch
static __device__ float g_attn[4096 * 1024];  // attention output scratch

__device__ __forceinline__ uint32_t f2tf(float x) {
    uint32_t u;
    asm("cvt.rna.tf32.f32 %0, %1;" : "=r"(u) : "f"(x));
    return u;
}
__device__ __forceinline__ float tf2f(float x) { return __uint_as_float(f2tf(x)); }
__device__ __forceinline__ float ex2f(float x) {
    float y;
    asm("ex2.approx.f32 %0, %1;" : "=f"(y) : "f"(x));
    return y;
}

// D(16x8) += A(16x8 tf32 row) * B(8x8 tf32 col)
__device__ __forceinline__ void mma_tf32(float* c, const uint32_t* a, uint32_t b0, uint32_t b1) {
    asm volatile(
        "mma.sync.aligned.m16n8k8.row.col.f32.tf32.tf32.f32 "
        "{%0,%1,%2,%3},{%4,%5,%6,%7},{%8,%9},{%0,%1,%2,%3};\n"
        : "+f"(c[0]), "+f"(c[1]), "+f"(c[2]), "+f"(c[3])
        : "r"(a[0]), "r"(a[1]), "r"(a[2]), "r"(a[3]), "r"(b0), "r"(b1));
}

// ============================================================================
// tf32 GEMM: C = scale * A[M,K] @ B[K,N]. CTA 128x128, BK=32, 256 thr, 8 warps.
// Fragment-paired smem layouts:
//   sA [128][40]: cols permuted so (c, c+4) adjacent -> A-frag via LDS.64
//   sB [16 u][264]: rows (k, k+4) interleaved per n  -> B-frag via LDS.64
// ============================================================================
#define GM_SA (128 * 40)
#define GM_SB (16 * 264)

__global__ __launch_bounds__(256) void gemm_tf32(
    const float* __restrict__ A, const float* __restrict__ Bm, float* __restrict__ C,
    int M, int N, int K, const float* __restrict__ scale_p)
{
    extern __shared__ float sm[];
    float* sA = sm;               // [2][128][40]
    float* sB = sm + 2 * GM_SA;   // [2][16][264]

    const int tid  = threadIdx.x;
    const int warp = tid >> 5, lane = tid & 31;
    const int wm = warp >> 2, wn = warp & 3;
    const int g = lane >> 2, q = lane & 3;
    const int bx = blockIdx.x, by = blockIdx.y;

    // A fill mapping: 4 iters p: row = (tid>>3)+p*32, unit j = tid&7
    const int ar  = tid >> 3;
    const int aj  = tid & 7;
    const int ac0 = (aj >> 1) * 8 + (aj & 1) * 2;
    // B fill mapping: 4 iters p: u = (tid>>6)+p*4, n = (tid&63)*2
    const int bu0 = tid >> 6;
    const int bn  = (tid & 63) * 2;
    const int bcol0 = bx * 128;

    float2 aR[4][2], bR[4][2];

    // ---- prologue: tile 0 ----
#pragma unroll
    for (int p = 0; p < 4; p++) {
        const float* src = &A[(size_t)(by * 128 + ar + p * 32) * K + ac0];
        aR[p][0] = *reinterpret_cast<const float2*>(src);
        aR[p][1] = *reinterpret_cast<const float2*>(src + 4);
    }
#pragma unroll
    for (int p = 0; p < 4; p++) {
        const int u = bu0 + p * 4;
        const int k0 = (u & 3) + ((u >> 2) << 3);
        const float* src = &Bm[(size_t)k0 * N + bcol0 + bn];
        bR[p][0] = *reinterpret_cast<const float2*>(src);
        bR[p][1] = *reinterpret_cast<const float2*>(src + (size_t)4 * N);
    }
#pragma unroll
    for (int p = 0; p < 4; p++) {
        float4 st = make_float4(tf2f(aR[p][0].x), tf2f(aR[p][1].x),
                                tf2f(aR[p][0].y), tf2f(aR[p][1].y));
        *reinterpret_cast<float4*>(&sA[(ar + p * 32) * 40 + aj * 4]) = st;
    }
#pragma unroll
    for (int p = 0; p < 4; p++) {
        const int u = bu0 + p * 4;
        float4 st = make_float4(tf2f(bR[p][0].x), tf2f(bR[p][1].x),
                                tf2f(bR[p][0].y), tf2f(bR[p][1].y));
        *reinterpret_cast<float4*>(&sB[u * 264 + bn * 2]) = st;
    }
    __syncthreads();

    float acc[4][4][4];
#pragma unroll
    for (int mf = 0; mf < 4; mf++)
#pragma unroll
        for (int nf = 0; nf < 4; nf++)
#pragma unroll
            for (int e = 0; e < 4; e++) acc[mf][nf][e] = 0.f;

    const int NK = K / 32;
    int cur = 0;
    for (int kt = 0; kt < NK; kt++) {
        if (kt + 1 < NK) {
            const int kc = (kt + 1) * 32;
#pragma unroll
            for (int p = 0; p < 4; p++) {
                const float* src = &A[(size_t)(by * 128 + ar + p * 32) * K + kc + ac0];
                aR[p][0] = *reinterpret_cast<const float2*>(src);
                aR[p][1] = *reinterpret_cast<const float2*>(src + 4);
            }
#pragma unroll
            for (int p = 0; p < 4; p++) {
                const int u = bu0 + p * 4;
                const int k0 = (u & 3) + ((u >> 2) << 3);
                const float* src = &Bm[(size_t)(kc + k0) * N + bcol0 + bn];
                bR[p][0] = *reinterpret_cast<const float2*>(src);
                bR[p][1] = *reinterpret_cast<const float2*>(src + (size_t)4 * N);
            }
        }
        const float* cA = sA + cur * GM_SA;
        const float* cB = sB + cur * GM_SB;
#pragma unroll
        for (int ks = 0; ks < 4; ks++) {
            uint32_t af[4][4];
#pragma unroll
            for (int mf = 0; mf < 4; mf++) {
                const int r = wm * 64 + mf * 16 + g;
                const float2 f0 = *reinterpret_cast<const float2*>(&cA[r * 40 + ks * 8 + q * 2]);
                const float2 f1 = *reinterpret_cast<const float2*>(&cA[(r + 8) * 40 + ks * 8 + q * 2]);
                af[mf][0] = __float_as_uint(f0.x);
                af[mf][1] = __float_as_uint(f1.x);
                af[mf][2] = __float_as_uint(f0.y);
                af[mf][3] = __float_as_uint(f1.y);
            }
#pragma unroll
            for (int nf = 0; nf < 4; nf++) {
                const int n = wn * 32 + nf * 8 + g;
                const float2 bb = *reinterpret_cast<const float2*>(&cB[(ks * 4 + q) * 264 + n * 2]);
                const uint32_t b0 = __float_as_uint(bb.x);
                const uint32_t b1 = __float_as_uint(bb.y);
#pragma unroll
                for (int mf = 0; mf < 4; mf++) mma_tf32(acc[mf][nf], af[mf], b0, b1);
            }
        }
        if (kt + 1 < NK) {
            float* dA = sA + (cur ^ 1) * GM_SA;
            float* dB = sB + (cur ^ 1) * GM_SB;
#pragma unroll
            for (int p = 0; p < 4; p++) {
                float4 st = make_float4(tf2f(aR[p][0].x), tf2f(aR[p][1].x),
                                        tf2f(aR[p][0].y), tf2f(aR[p][1].y));
                *reinterpret_cast<float4*>(&dA[(ar + p * 32) * 40 + aj * 4]) = st;
            }
#pragma unroll
            for (int p = 0; p < 4; p++) {
                const int u = bu0 + p * 4;
                float4 st = make_float4(tf2f(bR[p][0].x), tf2f(bR[p][1].x),
                                        tf2f(bR[p][0].y), tf2f(bR[p][1].y));
                *reinterpret_cast<float4*>(&dB[u * 264 + bn * 2]) = st;
            }
        }
        __syncthreads();
        cur ^= 1;
    }

    const float sc = scale_p ? *scale_p : 1.0f;
#pragma unroll
    for (int mf = 0; mf < 4; mf++) {
        const int r0 = by * 128 + wm * 64 + mf * 16 + g;
#pragma unroll
        for (int nf = 0; nf < 4; nf++) {
            const int c0 = bx * 128 + wn * 32 + nf * 8 + q * 2;
            *reinterpret_cast<float2*>(&C[(size_t)r0 * N + c0]) =
                make_float2(acc[mf][nf][0] * sc, acc[mf][nf][1] * sc);
            *reinterpret_cast<float2*>(&C[(size_t)(r0 + 8) * N + c0]) =
                make_float2(acc[mf][nf][2] * sc, acc[mf][nf][3] * sc);
        }
    }
}

// ============================================================================
// Fused flash attention, tf32 mma. CTA = 128 q-rows of one (b,h); 8 warps x 16.
// KV tile 128, processed as two 64-wide sub-tiles (halves score registers).
// Paired layouts: sK [128 kv][72] col-paired; sV [64 u][136] row-pair interleaved;
// sP [128][68] warp-private.
// ============================================================================
#define FK_FLOATS (128 * 72)
#define FV_FLOATS (64 * 136)
#define FP_FLOATS (128 * 68)

__global__ __launch_bounds__(256) void flash_tf32(
    const float* __restrict__ qkv, float* __restrict__ attn)
{
    extern __shared__ float sm[];
    float* sK = sm;
    float* sV = sm + FK_FLOATS;
    float* sP = sm + FK_FLOATS + FV_FLOATS;

    const int tid = threadIdx.x, warp = tid >> 5, lane = tid & 31;
    const int g = lane >> 2, q = lane & 3;
    const int qt = blockIdx.x, h = blockIdx.y, b = blockIdx.z;
    const float L2E = 1.4426950408889634f;

    const int qrow = b * 2048 + qt * 128 + warp * 16 + g;
    const int qcol = h * 64;

    // Q fragments, pre-scaled by 1/8 (exact)
    uint32_t qa[8][4];
#pragma unroll
    for (int ks = 0; ks < 8; ks++) {
        const int c = qcol + ks * 8 + q;
        qa[ks][0] = f2tf(qkv[(size_t)qrow * 3072 + c] * 0.125f);
        qa[ks][1] = f2tf(qkv[(size_t)(qrow + 8) * 3072 + c] * 0.125f);
        qa[ks][2] = f2tf(qkv[(size_t)qrow * 3072 + c + 4] * 0.125f);
        qa[ks][3] = f2tf(qkv[(size_t)(qrow + 8) * 3072 + c + 4] * 0.125f);
    }

    float m0 = -1e30f, m1 = -1e30f, l0 = 0.f, l1 = 0.f;
    float o[8][4];
#pragma unroll
    for (int nf = 0; nf < 8; nf++)
#pragma unroll
        for (int e = 0; e < 4; e++) o[nf][e] = 0.f;

    // fill mappings
    const int krr = tid >> 4;                 // + p*16
    const int kj  = tid & 15;
    const int kc0 = (kj >> 1) * 8 + (kj & 1) * 2;
    const int vu0 = tid >> 5;                 // + p*8
    const int vn  = (tid & 31) * 2;
    const int pr  = warp * 16 + g;            // warp-private P row

    for (int j = 0; j < 16; j++) {
        __syncthreads();
        const size_t kbase = (size_t)(b * 2048 + j * 128) * 3072 + 1024 + (size_t)h * 64;
        // K fill: col-paired (c, c+4)
#pragma unroll
        for (int p = 0; p < 8; p++) {
            const int rr = krr + p * 16;
            const float* src = &qkv[kbase + (size_t)rr * 3072 + kc0];
            const float2 ga = *reinterpret_cast<const float2*>(src);
            const float2 gb = *reinterpret_cast<const float2*>(src + 4);
            float4 st = make_float4(tf2f(ga.x), tf2f(gb.x), tf2f(ga.y), tf2f(gb.y));
            *reinterpret_cast<float4*>(&sK[rr * 72 + kj * 4]) = st;
        }
        // V fill: row-pair interleaved [u][n][sel]
#pragma unroll
        for (int p = 0; p < 8; p++) {
            const int u = vu0 + p * 8;
            const int k0 = (u & 3) + ((u >> 2) << 3);
            const float* src = &qkv[kbase + 1024 + (size_t)k0 * 3072 + vn];
            const float2 ga = *reinterpret_cast<const float2*>(src);
            const float2 gb = *reinterpret_cast<const float2*>(src + (size_t)4 * 3072);
            float4 st = make_float4(tf2f(ga.x), tf2f(gb.x), tf2f(ga.y), tf2f(gb.y));
            *reinterpret_cast<float4*>(&sV[u * 136 + vn * 2]) = st;
        }
        __syncthreads();

#pragma unroll
        for (int jj = 0; jj < 2; jj++) {
            // S = Q @ K^T over 64 kv cols
            float s[8][4];
#pragma unroll
            for (int nf = 0; nf < 8; nf++)
#pragma unroll
                for (int e = 0; e < 4; e++) s[nf][e] = 0.f;
#pragma unroll
            for (int ks = 0; ks < 8; ks++) {
#pragma unroll
                for (int nf = 0; nf < 8; nf++) {
                    const int nrow = jj * 64 + nf * 8 + g;
                    const float2 bb = *reinterpret_cast<const float2*>(&sK[nrow * 72 + ks * 8 + q * 2]);
                    mma_tf32(s[nf], qa[ks], __float_as_uint(bb.x), __float_as_uint(bb.y));
                }
            }

            // online softmax update
            float rm0 = -1e30f, rm1 = -1e30f;
#pragma unroll
            for (int nf = 0; nf < 8; nf++) {
                rm0 = fmaxf(rm0, fmaxf(s[nf][0], s[nf][1]));
                rm1 = fmaxf(rm1, fmaxf(s[nf][2], s[nf][3]));
            }
            rm0 = fmaxf(rm0, __shfl_xor_sync(0xffffffffu, rm0, 1));
            rm0 = fmaxf(rm0, __shfl_xor_sync(0xffffffffu, rm0, 2));
            rm1 = fmaxf(rm1, __shfl_xor_sync(0xffffffffu, rm1, 1));
            rm1 = fmaxf(rm1, __shfl_xor_sync(0xffffffffu, rm1, 2));
            const float mn0 = fmaxf(m0, rm0), mn1 = fmaxf(m1, rm1);
            const float al0 = ex2f((m0 - mn0) * L2E), al1 = ex2f((m1 - mn1) * L2E);
            const float mb0 = mn0 * L2E, mb1 = mn1 * L2E;

            float rs0 = 0.f, rs1 = 0.f;
#pragma unroll
            for (int nf = 0; nf < 8; nf++) {
                const float p0 = tf2f(ex2f(fmaf(s[nf][0], L2E, -mb0)));
                const float p1 = tf2f(ex2f(fmaf(s[nf][1], L2E, -mb0)));
                const float p2 = tf2f(ex2f(fmaf(s[nf][2], L2E, -mb1)));
                const float p3 = tf2f(ex2f(fmaf(s[nf][3], L2E, -mb1)));
                rs0 += p0 + p1;
                rs1 += p2 + p3;
                *reinterpret_cast<float2*>(&sP[pr * 68 + nf * 8 + q * 2]) = make_float2(p0, p1);
                *reinterpret_cast<float2*>(&sP[(pr + 8) * 68 + nf * 8 + q * 2]) = make_float2(p2, p3);
            }
            rs0 += __shfl_xor_sync(0xffffffffu, rs0, 1);
            rs0 += __shfl_xor_sync(0xffffffffu, rs0, 2);
            rs1 += __shfl_xor_sync(0xffffffffu, rs1, 1);
            rs1 += __shfl_xor_sync(0xffffffffu, rs1, 2);
            l0 = l0 * al0 + rs0;
            l1 = l1 * al1 + rs1;
            m0 = mn0; m1 = mn1;
#pragma unroll
            for (int nf = 0; nf < 8; nf++) {
                o[nf][0] *= al0; o[nf][1] *= al0; o[nf][2] *= al1; o[nf][3] *= al1;
            }
            __syncwarp();  // sP stores visible within warp

            // O += P @ V over this 64-kv sub-tile
#pragma unroll
            for (int kb = 0; kb < 8; kb++) {
                uint32_t pa[4];
                pa[0] = __float_as_uint(sP[pr * 68 + kb * 8 + q]);
                pa[1] = __float_as_uint(sP[(pr + 8) * 68 + kb * 8 + q]);
                pa[2] = __float_as_uint(sP[pr * 68 + kb * 8 + q + 4]);
                pa[3] = __float_as_uint(sP[(pr + 8) * 68 + kb * 8 + q + 4]);
                const int u = (jj * 8 + kb) * 4 + q;
#pragma unroll
                for (int nf = 0; nf < 8; nf++) {
                    const float2 bb = *reinterpret_cast<const float2*>(&sV[u * 136 + (nf * 8 + g) * 2]);
                    mma_tf32(o[nf], pa, __float_as_uint(bb.x), __float_as_uint(bb.y));
                }
            }
            __syncwarp();  // P reads done before next sub-tile overwrites sP
        }
    }

    const float il0 = 1.f / l0, il1 = 1.f / l1;
#pragma unroll
    for (int nf = 0; nf < 8; nf++) {
        const int c = h * 64 + nf * 8 + q * 2;
        *reinterpret_cast<float2*>(&attn[(size_t)qrow * 1024 + c]) =
            make_float2(o[nf][0] * il0, o[nf][1] * il0);
        *reinterpret_cast<float2*>(&attn[(size_t)(qrow + 8) * 1024 + c]) =
            make_float2(o[nf][2] * il1, o[nf][3] * il1);
    }
}

// ============================================================================
extern "C" void kernel_launch(void* const* d_in, const int* in_sizes, int n_in,
                              void* d_out, int out_size)
{
    const float* hidden = (const float*)d_in[0];
    const float* qkvw   = (const float*)d_in[1];
    const float* ow     = (const float*)d_in[2];
    const float* ssm    = (const float*)d_in[4];
    float* out = (float*)d_out;
    (void)in_sizes; (void)n_in; (void)out_size;

    const int smem_g = (2 * GM_SA + 2 * GM_SB) * 4;                    // 74752 B
    const int smem_f = (FK_FLOATS + FV_FLOATS + FP_FLOATS) * 4;        // 106496 B
    cudaFuncSetAttribute(gemm_tf32, cudaFuncAttributeMaxDynamicSharedMemorySize, smem_g);
    cudaFuncSetAttribute(flash_tf32, cudaFuncAttributeMaxDynamicSharedMemorySize, smem_f);

    float *qkvp, *attnp;
    cudaGetSymbolAddress((void**)&qkvp, g_qkv);
    cudaGetSymbolAddress((void**)&attnp, g_attn);

    gemm_tf32<<<dim3(3072 / 128, 4096 / 128), 256, smem_g>>>(
        hidden, qkvw, qkvp, 4096, 3072, 1024, nullptr);

    flash_tf32<<<dim3(16, 16, 2), 256, smem_f>>>(qkvp, attnp);

    gemm_tf32<<<dim3(1024 / 128, 4096 / 128), 256, smem_g>>>(
        attnp, ow, out, 4096, 1024, 1024, ssm);
}

// round 9
// speedup vs baseline: 1.2601x; 1.2601x over previous
#include <cuda_runtime.h>
#include <cstdint>

// Problem constants: B=2, S=2048, H=1024, NH=16, D=64; M = B*S = 4096

static __device__ float g_qkv[4096 * 3072];   // qkv projection scratch
static __device__ float g_attn[4096 * 1024];  // attention output scratch

__device__ __forceinline__ uint32_t f2tf(float x) {
    uint32_t u;
    asm("cvt.rna.tf32.f32 %0, %1;" : "=r"(u) : "f"(x));
    return u;
}
__device__ __forceinline__ float tf2f(float x) { return __uint_as_float(f2tf(x)); }
__device__ __forceinline__ float ex2f(float x) {
    float y;
    asm("ex2.approx.f32 %0, %1;" : "=f"(y) : "f"(x));
    return y;
}

// D(16x8) += A(16x8 tf32 row) * B(8x8 tf32 col)
__device__ __forceinline__ void mma_tf32(float* c, const uint32_t* a, uint32_t b0, uint32_t b1) {
    asm volatile(
        "mma.sync.aligned.m16n8k8.row.col.f32.tf32.tf32.f32 "
        "{%0,%1,%2,%3},{%4,%5,%6,%7},{%8,%9},{%0,%1,%2,%3};\n"
        : "+f"(c[0]), "+f"(c[1]), "+f"(c[2]), "+f"(c[3])
        : "r"(a[0]), "r"(a[1]), "r"(a[2]), "r"(a[3]), "r"(b0), "r"(b1));
}

// ============================================================================
// tf32 GEMM (R1 version, known-good 200us): C = scale * A[M,K] @ B[K,N]
// CTA tile 128x128, BK=32, 256 threads, warp tile 64x32. Double-buffered smem.
// __launch_bounds__(256,2) pins the 2-CTA/SM working point (regs <= 128).
// ============================================================================
#define GM_SA (128 * 36)   // A tile 128x32, row stride 36
#define GM_SB (32 * 136)   // B tile 32x128, row stride 136

__global__ __launch_bounds__(256, 2) void gemm_tf32(
    const float* __restrict__ A, const float* __restrict__ Bm, float* __restrict__ C,
    int M, int N, int K, const float* __restrict__ scale_p)
{
    extern __shared__ float sm[];
    float* sA = sm;               // [2][128][36]
    float* sB = sm + 2 * GM_SA;   // [2][32][136]

    const int tid  = threadIdx.x;
    const int warp = tid >> 5, lane = tid & 31;
    const int wm = warp >> 2, wn = warp & 3;
    const int g = lane >> 2, q = lane & 3;
    const int bx = blockIdx.x, by = blockIdx.y;

    const int arow = by * 128 + (tid >> 3);
    const int ac4  = (tid & 7) * 4;
    const int brow = (tid >> 5);
    const int bcol = bx * 128 + (tid & 31) * 4;

    float4 aR[4], bR[4];
#pragma unroll
    for (int p = 0; p < 4; p++)
        aR[p] = *reinterpret_cast<const float4*>(&A[(size_t)(arow + p * 32) * K + ac4]);
#pragma unroll
    for (int p = 0; p < 4; p++)
        bR[p] = *reinterpret_cast<const float4*>(&Bm[(size_t)(brow + p * 8) * N + bcol]);

#pragma unroll
    for (int p = 0; p < 4; p++) {
        float* d = &sA[((tid >> 3) + p * 32) * 36 + ac4];
        d[0] = tf2f(aR[p].x); d[1] = tf2f(aR[p].y); d[2] = tf2f(aR[p].z); d[3] = tf2f(aR[p].w);
    }
#pragma unroll
    for (int p = 0; p < 4; p++) {
        float* d = &sB[(brow + p * 8) * 136 + (tid & 31) * 4];
        d[0] = tf2f(bR[p].x); d[1] = tf2f(bR[p].y); d[2] = tf2f(bR[p].z); d[3] = tf2f(bR[p].w);
    }
    __syncthreads();

    float acc[4][4][4];
#pragma unroll
    for (int mf = 0; mf < 4; mf++)
#pragma unroll
        for (int nf = 0; nf < 4; nf++)
#pragma unroll
            for (int e = 0; e < 4; e++) acc[mf][nf][e] = 0.f;

    const int NK = K / 32;
    int cur = 0;
    for (int kt = 0; kt < NK; kt++) {
        if (kt + 1 < NK) {
            const int kc = (kt + 1) * 32;
#pragma unroll
            for (int p = 0; p < 4; p++)
                aR[p] = *reinterpret_cast<const float4*>(&A[(size_t)(arow + p * 32) * K + kc + ac4]);
#pragma unroll
            for (int p = 0; p < 4; p++)
                bR[p] = *reinterpret_cast<const float4*>(&Bm[(size_t)(kc + brow + p * 8) * N + bcol]);
        }
        const float* cA = sA + cur * GM_SA;
        const float* cB = sB + cur * GM_SB;
#pragma unroll
        for (int ks = 0; ks < 4; ks++) {
            uint32_t af[4][4];
#pragma unroll
            for (int mf = 0; mf < 4; mf++) {
                const int r = wm * 64 + mf * 16 + g;
                const int c = ks * 8 + q;
                af[mf][0] = __float_as_uint(cA[r * 36 + c]);
                af[mf][1] = __float_as_uint(cA[(r + 8) * 36 + c]);
                af[mf][2] = __float_as_uint(cA[r * 36 + c + 4]);
                af[mf][3] = __float_as_uint(cA[(r + 8) * 36 + c + 4]);
            }
#pragma unroll
            for (int nf = 0; nf < 4; nf++) {
                const int n = wn * 32 + nf * 8 + g;
                const int k = ks * 8 + q;
                const uint32_t b0 = __float_as_uint(cB[k * 136 + n]);
                const uint32_t b1 = __float_as_uint(cB[(k + 4) * 136 + n]);
#pragma unroll
                for (int mf = 0; mf < 4; mf++) mma_tf32(acc[mf][nf], af[mf], b0, b1);
            }
        }
        if (kt + 1 < NK) {
            float* dA = sA + (cur ^ 1) * GM_SA;
            float* dB = sB + (cur ^ 1) * GM_SB;
#pragma unroll
            for (int p = 0; p < 4; p++) {
                float* d = &dA[((tid >> 3) + p * 32) * 36 + ac4];
                d[0] = tf2f(aR[p].x); d[1] = tf2f(aR[p].y); d[2] = tf2f(aR[p].z); d[3] = tf2f(aR[p].w);
            }
#pragma unroll
            for (int p = 0; p < 4; p++) {
                float* d = &dB[(brow + p * 8) * 136 + (tid & 31) * 4];
                d[0] = tf2f(bR[p].x); d[1] = tf2f(bR[p].y); d[2] = tf2f(bR[p].z); d[3] = tf2f(bR[p].w);
            }
        }
        __syncthreads();
        cur ^= 1;
    }

    const float sc = scale_p ? *scale_p : 1.0f;
#pragma unroll
    for (int mf = 0; mf < 4; mf++) {
        const int r0 = by * 128 + wm * 64 + mf * 16 + g;
#pragma unroll
        for (int nf = 0; nf < 4; nf++) {
            const int c0 = bx * 128 + wn * 32 + nf * 8 + q * 2;
            *reinterpret_cast<float2*>(&C[(size_t)r0 * N + c0]) =
                make_float2(acc[mf][nf][0] * sc, acc[mf][nf][1] * sc);
            *reinterpret_cast<float2*>(&C[(size_t)(r0 + 8) * N + c0]) =
                make_float2(acc[mf][nf][2] * sc, acc[mf][nf][3] * sc);
        }
    }
}

// ============================================================================
// Fused flash attention, tf32 mma, SPLIT-KV warp pairs.
// CTA = 64 q-rows of one (b,h); 8 warps = 4 pairs; pair shares 16 q-rows,
// each warp of a pair owns a 64-wide half of the 128-wide KV tile.
// Halves per-warp score regs AND smem (105.5KB -> 2 CTAs/SM, 16 warps).
// Per-tile m/l merged across the pair via tiny smem arrays + CTA barriers.
// ============================================================================
#define FK_FLOATS (128 * 68)   // sK: kv row x d col (B-op of QK)
#define FV_FLOATS (128 * 72)   // sV: kv k x d n   (B-op of PV)
#define FP_FLOATS (64 * 132)   // sP: 64 q-rows x 128 kv cols (A-op of PV)
#define FM_FLOATS (64 * 2)
#define FL_FLOATS (64 * 2)

__global__ __launch_bounds__(256, 2) void flash_tf32(
    const float* __restrict__ qkv, float* __restrict__ attn)
{
    extern __shared__ float sm[];
    float* sK = sm;
    float* sV = sK + FK_FLOATS;
    float* sP = sV + FV_FLOATS;
    float* sM = sP + FP_FLOATS;
    float* sL = sM + FM_FLOATS;

    const int tid = threadIdx.x, warp = tid >> 5, lane = tid & 31;
    const int g = lane >> 2, q = lane & 3;
    const int pairid = warp >> 1, half = warp & 1;
    const int qt = blockIdx.x, h = blockIdx.y, b = blockIdx.z;
    const float L2E = 1.4426950408889634f;

    const int row0 = pairid * 16 + g;          // local q-row (0..63)
    const int row1 = row0 + 8;
    const int qrow = b * 2048 + qt * 64 + row0; // global q-row
    const int qcol = h * 64;

    // Q fragments, pre-scaled by 1/sqrt(64)=0.125 (exact in tf32)
    uint32_t qa[8][4];
#pragma unroll
    for (int ks = 0; ks < 8; ks++) {
        const int c = qcol + ks * 8 + q;
        qa[ks][0] = f2tf(qkv[(size_t)qrow * 3072 + c] * 0.125f);
        qa[ks][1] = f2tf(qkv[(size_t)(qrow + 8) * 3072 + c] * 0.125f);
        qa[ks][2] = f2tf(qkv[(size_t)qrow * 3072 + c + 4] * 0.125f);
        qa[ks][3] = f2tf(qkv[(size_t)(qrow + 8) * 3072 + c + 4] * 0.125f);
    }

    float m0 = -1e30f, m1 = -1e30f, l0 = 0.f, l1 = 0.f;
    float o[8][4];
#pragma unroll
    for (int nf = 0; nf < 8; nf++)
#pragma unroll
        for (int e = 0; e < 4; e++) o[nf][e] = 0.f;

    const int rr0 = tid >> 4;        // K/V fill: rows rr0 + p*16
    const int dd  = (tid & 15) * 4;

    for (int j = 0; j < 16; j++) {
        __syncthreads();  // prior tile's sK/sV reads complete
        const size_t kvbase = (size_t)(b * 2048 + j * 128) * 3072 + 1024 + (size_t)h * 64;
#pragma unroll
        for (int p = 0; p < 8; p++) {
            const int rr = rr0 + p * 16;
            const float4 kx = *reinterpret_cast<const float4*>(&qkv[kvbase + (size_t)rr * 3072 + dd]);
            float* dk = &sK[rr * 68 + dd];
            dk[0] = tf2f(kx.x); dk[1] = tf2f(kx.y); dk[2] = tf2f(kx.z); dk[3] = tf2f(kx.w);
            const float4 vx = *reinterpret_cast<const float4*>(&qkv[kvbase + 1024 + (size_t)rr * 3072 + dd]);
            float* dv = &sV[rr * 72 + dd];
            dv[0] = tf2f(vx.x); dv[1] = tf2f(vx.y); dv[2] = tf2f(vx.z); dv[3] = tf2f(vx.w);
        }
        __syncthreads();  // fill visible

        // S = Q @ K^T over this warp's 64 kv cols
        float s[8][4];
#pragma unroll
        for (int nf = 0; nf < 8; nf++)
#pragma unroll
            for (int e = 0; e < 4; e++) s[nf][e] = 0.f;
#pragma unroll
        for (int ks = 0; ks < 8; ks++) {
#pragma unroll
            for (int nf = 0; nf < 8; nf++) {
                const int nrow = half * 64 + nf * 8 + g;
                const uint32_t b0 = __float_as_uint(sK[nrow * 68 + ks * 8 + q]);
                const uint32_t b1 = __float_as_uint(sK[nrow * 68 + ks * 8 + q + 4]);
                mma_tf32(s[nf], qa[ks], b0, b1);
            }
        }

        // local (half) row max, reduce within quad
        float rm0 = -1e30f, rm1 = -1e30f;
#pragma unroll
        for (int nf = 0; nf < 8; nf++) {
            rm0 = fmaxf(rm0, fmaxf(s[nf][0], s[nf][1]));
            rm1 = fmaxf(rm1, fmaxf(s[nf][2], s[nf][3]));
        }
        rm0 = fmaxf(rm0, __shfl_xor_sync(0xffffffffu, rm0, 1));
        rm0 = fmaxf(rm0, __shfl_xor_sync(0xffffffffu, rm0, 2));
        rm1 = fmaxf(rm1, __shfl_xor_sync(0xffffffffu, rm1, 1));
        rm1 = fmaxf(rm1, __shfl_xor_sync(0xffffffffu, rm1, 2));
        if (q == 0) {
            sM[row0 * 2 + half] = rm0;
            sM[row1 * 2 + half] = rm1;
        }
        __syncthreads();  // m exchange across the pair

        const float rmA0 = fmaxf(sM[row0 * 2], sM[row0 * 2 + 1]);
        const float rmA1 = fmaxf(sM[row1 * 2], sM[row1 * 2 + 1]);
        const float mn0 = fmaxf(m0, rmA0), mn1 = fmaxf(m1, rmA1);
        const float al0 = ex2f((m0 - mn0) * L2E), al1 = ex2f((m1 - mn1) * L2E);
        const float mb0 = mn0 * L2E, mb1 = mn1 * L2E;

        float rs0 = 0.f, rs1 = 0.f;
#pragma unroll
        for (int nf = 0; nf < 8; nf++) {
            const float p0 = tf2f(ex2f(fmaf(s[nf][0], L2E, -mb0)));
            const float p1 = tf2f(ex2f(fmaf(s[nf][1], L2E, -mb0)));
            const float p2 = tf2f(ex2f(fmaf(s[nf][2], L2E, -mb1)));
            const float p3 = tf2f(ex2f(fmaf(s[nf][3], L2E, -mb1)));
            rs0 += p0 + p1;
            rs1 += p2 + p3;
            const int c = half * 64 + nf * 8 + q * 2;
            *reinterpret_cast<float2*>(&sP[row0 * 132 + c]) = make_float2(p0, p1);
            *reinterpret_cast<float2*>(&sP[row1 * 132 + c]) = make_float2(p2, p3);
        }
        rs0 += __shfl_xor_sync(0xffffffffu, rs0, 1);
        rs0 += __shfl_xor_sync(0xffffffffu, rs0, 2);
        rs1 += __shfl_xor_sync(0xffffffffu, rs1, 1);
        rs1 += __shfl_xor_sync(0xffffffffu, rs1, 2);
        if (q == 0) {
            sL[row0 * 2 + half] = rs0;
            sL[row1 * 2 + half] = rs1;
        }
        __syncthreads();  // l exchange (also orders sP stores before PV reads)

        l0 = l0 * al0 + sL[row0 * 2] + sL[row0 * 2 + 1];
        l1 = l1 * al1 + sL[row1 * 2] + sL[row1 * 2 + 1];
        m0 = mn0; m1 = mn1;
#pragma unroll
        for (int nf = 0; nf < 8; nf++) {
            o[nf][0] *= al0; o[nf][1] *= al0; o[nf][2] *= al1; o[nf][3] *= al1;
        }

        // O += P_half @ V_half (this warp's 64 kv rows)
#pragma unroll
        for (int kb = 0; kb < 8; kb++) {
            const int c = half * 64 + kb * 8 + q;
            uint32_t pa[4];
            pa[0] = __float_as_uint(sP[row0 * 132 + c]);
            pa[1] = __float_as_uint(sP[row1 * 132 + c]);
            pa[2] = __float_as_uint(sP[row0 * 132 + c + 4]);
            pa[3] = __float_as_uint(sP[row1 * 132 + c + 4]);
#pragma unroll
            for (int nf = 0; nf < 8; nf++) {
                const uint32_t b0 = __float_as_uint(sV[c * 72 + nf * 8 + g]);
                const uint32_t b1 = __float_as_uint(sV[(c + 4) * 72 + nf * 8 + g]);
                mma_tf32(o[nf], pa, b0, b1);
            }
        }
    }

    // ---- pair merge: O = (O_half0 + O_half1) / l ----
    __syncthreads();  // all PV reads done; sP free for reuse
    if (half == 1) {
#pragma unroll
        for (int nf = 0; nf < 8; nf++) {
            const int c = nf * 8 + q * 2;
            *reinterpret_cast<float2*>(&sP[row0 * 132 + c]) = make_float2(o[nf][0], o[nf][1]);
            *reinterpret_cast<float2*>(&sP[row1 * 132 + c]) = make_float2(o[nf][2], o[nf][3]);
        }
    }
    __syncthreads();
    if (half == 0) {
        const float il0 = 1.f / l0, il1 = 1.f / l1;
#pragma unroll
        for (int nf = 0; nf < 8; nf++) {
            const int c = nf * 8 + q * 2;
            const float2 p0 = *reinterpret_cast<const float2*>(&sP[row0 * 132 + c]);
            const float2 p1 = *reinterpret_cast<const float2*>(&sP[row1 * 132 + c]);
            const int gc = h * 64 + c;
            *reinterpret_cast<float2*>(&attn[(size_t)qrow * 1024 + gc]) =
                make_float2((o[nf][0] + p0.x) * il0, (o[nf][1] + p0.y) * il0);
            *reinterpret_cast<float2*>(&attn[(size_t)(qrow + 8) * 1024 + gc]) =
                make_float2((o[nf][2] + p1.x) * il1, (o[nf][3] + p1.y) * il1);
        }
    }
}

// ============================================================================
extern "C" void kernel_launch(void* const* d_in, const int* in_sizes, int n_in,
                              void* d_out, int out_size)
{
    const float* hidden = (const float*)d_in[0];
    const float* qkvw   = (const float*)d_in[1];
    const float* ow     = (const float*)d_in[2];
    const float* ssm    = (const float*)d_in[4];
    float* out = (float*)d_out;
    (void)in_sizes; (void)n_in; (void)out_size;

    const int smem_g = (2 * GM_SA + 2 * GM_SB) * 4;   // 71680 B
    const int smem_f = (FK_FLOATS + FV_FLOATS + FP_FLOATS + FM_FLOATS + FL_FLOATS) * 4; // 105472 B
    cudaFuncSetAttribute(gemm_tf32, cudaFuncAttributeMaxDynamicSharedMemorySize, smem_g);
    cudaFuncSetAttribute(flash_tf32, cudaFuncAttributeMaxDynamicSharedMemorySize, smem_f);

    float *qkvp, *attnp;
    cudaGetSymbolAddress((void**)&qkvp, g_qkv);
    cudaGetSymbolAddress((void**)&attnp, g_attn);

    // QKV projection: [4096,1024] @ [1024,3072]
    gemm_tf32<<<dim3(3072 / 128, 4096 / 128), 256, smem_g>>>(
        hidden, qkvw, qkvp, 4096, 3072, 1024, nullptr);

    // attention: per (b, h, 64-row qtile)
    flash_tf32<<<dim3(32, 16, 2), 256, smem_f>>>(qkvp, attnp);

    // O projection with scaled_softmax folded in
    gemm_tf32<<<dim3(1024 / 128, 4096 / 128), 256, smem_g>>>(
        attnp, ow, out, 4096, 1024, 1024, ssm);
}

// round 17
// speedup vs baseline: 1.2775x; 1.0138x over previous
#include <cuda_runtime.h>
#include <cstdint>

// Problem constants: B=2, S=2048, H=1024, NH=16, D=64; M = B*S = 4096
// NOTE: harness PTX target is compute_103 (no 'a') -> tcgen05 unavailable.
// Legacy mma.sync tf32 is the tensor path; bottleneck is LDS issue count ->
// this round converts fragment loads to ldmatrix (LDSM).

static __device__ float g_qkv[4096 * 3072];   // qkv projection scratch
static __device__ float g_attn[4096 * 1024];  // attention output scratch

__device__ __forceinline__ uint32_t f2tf(float x) {
    uint32_t u;
    asm("cvt.rna.tf32.f32 %0, %1;" : "=r"(u) : "f"(x));
    return u;
}
__device__ __forceinline__ float tf2f(float x) { return __uint_as_float(f2tf(x)); }
__device__ __forceinline__ float ex2f(float x) {
    float y;
    asm("ex2.approx.f32 %0, %1;" : "=f"(y) : "f"(x));
    return y;
}
__device__ __forceinline__ uint32_t s2u(const void* p) {
    uint32_t a;
    asm("{ .reg .u64 t; cvta.to.shared.u64 t, %1; cvt.u32.u64 %0, t; }" : "=r"(a) : "l"(p));
    return a;
}
// D(16x8) += A(16x8 tf32 row) * B(8x8 tf32 col)
__device__ __forceinline__ void mma_tf32(float* c, const uint32_t* a, uint32_t b0, uint32_t b1) {
    asm volatile(
        "mma.sync.aligned.m16n8k8.row.col.f32.tf32.tf32.f32 "
        "{%0,%1,%2,%3},{%4,%5,%6,%7},{%8,%9},{%0,%1,%2,%3};\n"
        : "+f"(c[0]), "+f"(c[1]), "+f"(c[2]), "+f"(c[3])
        : "r"(a[0]), "r"(a[1]), "r"(a[2]), "r"(a[3]), "r"(b0), "r"(b1));
}
// ldmatrix x4 (b16 view; works for tf32: lane j -> row j/4, 32-bit col j%4)
__device__ __forceinline__ void ldsm4(uint32_t* r, uint32_t addr) {
    asm volatile("ldmatrix.sync.aligned.m8n8.x4.shared.b16 {%0,%1,%2,%3}, [%4];"
                 : "=r"(r[0]), "=r"(r[1]), "=r"(r[2]), "=r"(r[3]) : "r"(addr));
}

// ============================================================================
// tf32 GEMM (R1 design + LDSM A-fragments): C = scale * A[M,K] @ B[K,N]
// CTA tile 128x128, BK=32, 256 threads, warp tile 64x32. Double-buffered.
// __launch_bounds__(256,2) pins 2 CTA/SM (regs <= 128).
// ============================================================================
#define GM_SA (128 * 36)   // A tile 128x32, row stride 36 (LDSM conflict-free)
#define GM_SB (32 * 136)   // B tile 32x128, row stride 136

__global__ __launch_bounds__(256, 2) void gemm_tf32(
    const float* __restrict__ A, const float* __restrict__ Bm, float* __restrict__ C,
    int M, int N, int K, const float* __restrict__ scale_p)
{
    extern __shared__ float sm[];
    float* sA = sm;               // [2][128][36]
    float* sB = sm + 2 * GM_SA;   // [2][32][136]

    const int tid  = threadIdx.x;
    const int warp = tid >> 5, lane = tid & 31;
    const int wm = warp >> 2, wn = warp & 3;
    const int g = lane >> 2, q = lane & 3;
    const int bx = blockIdx.x, by = blockIdx.y;

    const int arow = by * 128 + (tid >> 3);
    const int ac4  = (tid & 7) * 4;
    const int brow = (tid >> 5);
    const int bcol = bx * 128 + (tid & 31) * 4;

    // LDSM addressing for A fragments: lanes 0-7 m0(rows r..r+7, col+0),
    // 8-15 m1(rows r+8.., col+0), 16-23 m2(rows r.., col+4), 24-31 m3(r+8, +4)
    const int lrow  = (lane & 7) + ((lane >> 3) & 1) * 8;
    const uint32_t lcolb = ((lane >> 4) & 1) * 16;   // bytes
    uint32_t aoff[4];
#pragma unroll
    for (int mf = 0; mf < 4; mf++)
        aoff[mf] = (uint32_t)((wm * 64 + mf * 16 + lrow) * 36 * 4) + lcolb;

    float4 aR[4], bR[4];
#pragma unroll
    for (int p = 0; p < 4; p++)
        aR[p] = *reinterpret_cast<const float4*>(&A[(size_t)(arow + p * 32) * K + ac4]);
#pragma unroll
    for (int p = 0; p < 4; p++)
        bR[p] = *reinterpret_cast<const float4*>(&Bm[(size_t)(brow + p * 8) * N + bcol]);

#pragma unroll
    for (int p = 0; p < 4; p++) {
        float* d = &sA[((tid >> 3) + p * 32) * 36 + ac4];
        d[0] = tf2f(aR[p].x); d[1] = tf2f(aR[p].y); d[2] = tf2f(aR[p].z); d[3] = tf2f(aR[p].w);
    }
#pragma unroll
    for (int p = 0; p < 4; p++) {
        float* d = &sB[(brow + p * 8) * 136 + (tid & 31) * 4];
        d[0] = tf2f(bR[p].x); d[1] = tf2f(bR[p].y); d[2] = tf2f(bR[p].z); d[3] = tf2f(bR[p].w);
    }
    __syncthreads();

    float acc[4][4][4];
#pragma unroll
    for (int mf = 0; mf < 4; mf++)
#pragma unroll
        for (int nf = 0; nf < 4; nf++)
#pragma unroll
            for (int e = 0; e < 4; e++) acc[mf][nf][e] = 0.f;

    const int NK = K / 32;
    int cur = 0;
    for (int kt = 0; kt < NK; kt++) {
        if (kt + 1 < NK) {
            const int kc = (kt + 1) * 32;
#pragma unroll
            for (int p = 0; p < 4; p++)
                aR[p] = *reinterpret_cast<const float4*>(&A[(size_t)(arow + p * 32) * K + kc + ac4]);
#pragma unroll
            for (int p = 0; p < 4; p++)
                bR[p] = *reinterpret_cast<const float4*>(&Bm[(size_t)(kc + brow + p * 8) * N + bcol]);
        }
        const float* cA = sA + cur * GM_SA;
        const float* cB = sB + cur * GM_SB;
        const uint32_t abase = s2u(cA);
#pragma unroll
        for (int ks = 0; ks < 4; ks++) {
            uint32_t af[4][4];
#pragma unroll
            for (int mf = 0; mf < 4; mf++)
                ldsm4(af[mf], abase + aoff[mf] + ks * 32);
#pragma unroll
            for (int nf = 0; nf < 4; nf++) {
                const int n = wn * 32 + nf * 8 + g;
                const int k = ks * 8 + q;
                const uint32_t b0 = __float_as_uint(cB[k * 136 + n]);
                const uint32_t b1 = __float_as_uint(cB[(k + 4) * 136 + n]);
#pragma unroll
                for (int mf = 0; mf < 4; mf++) mma_tf32(acc[mf][nf], af[mf], b0, b1);
            }
        }
        if (kt + 1 < NK) {
            float* dA = sA + (cur ^ 1) * GM_SA;
            float* dB = sB + (cur ^ 1) * GM_SB;
#pragma unroll
            for (int p = 0; p < 4; p++) {
                float* d = &dA[((tid >> 3) + p * 32) * 36 + ac4];
                d[0] = tf2f(aR[p].x); d[1] = tf2f(aR[p].y); d[2] = tf2f(aR[p].z); d[3] = tf2f(aR[p].w);
            }
#pragma unroll
            for (int p = 0; p < 4; p++) {
                float* d = &dB[(brow + p * 8) * 136 + (tid & 31) * 4];
                d[0] = tf2f(bR[p].x); d[1] = tf2f(bR[p].y); d[2] = tf2f(bR[p].z); d[3] = tf2f(bR[p].w);
            }
        }
        __syncthreads();
        cur ^= 1;
    }

    const float sc = scale_p ? *scale_p : 1.0f;
#pragma unroll
    for (int mf = 0; mf < 4; mf++) {
        const int r0 = by * 128 + wm * 64 + mf * 16 + g;
#pragma unroll
        for (int nf = 0; nf < 4; nf++) {
            const int c0 = bx * 128 + wn * 32 + nf * 8 + q * 2;
            *reinterpret_cast<float2*>(&C[(size_t)r0 * N + c0]) =
                make_float2(acc[mf][nf][0] * sc, acc[mf][nf][1] * sc);
            *reinterpret_cast<float2*>(&C[(size_t)(r0 + 8) * N + c0]) =
                make_float2(acc[mf][nf][2] * sc, acc[mf][nf][3] * sc);
        }
    }
}

// ============================================================================
// Fused flash attention (R1 structure + LDSM fragment loads).
// CTA = 128 q-rows of one (b,h); 8 warps x 16 q-rows; KV tiles of 128.
// sK [128 kv][68 d]  (QK B-op, LDSM)
// sVt [64 d][132 kv] (PV B-op, transposed fill -> LDSM)
// sP [128][132]      (PV A-op, warp-private, LDSM)
// ============================================================================
#define FA_SK  (128 * 68)
#define FA_SVT (64 * 132)
#define FA_SP  (128 * 132)

__global__ __launch_bounds__(256) void flash_tf32(
    const float* __restrict__ qkv, float* __restrict__ attn)
{
    extern __shared__ float sm[];
    float* sK  = sm;
    float* sVt = sm + FA_SK;
    float* sP  = sm + FA_SK + FA_SVT;

    const int tid = threadIdx.x, warp = tid >> 5, lane = tid & 31;
    const int g = lane >> 2, q = lane & 3;
    const int qt = blockIdx.x, h = blockIdx.y, b = blockIdx.z;
    const float L2E = 1.4426950408889634f;

    const int qrow = b * 2048 + qt * 128 + warp * 16 + g;
    const int qcol = h * 64;

    uint32_t qa[8][4];
#pragma unroll
    for (int ks = 0; ks < 8; ks++) {
        const int c = qcol + ks * 8 + q;
        qa[ks][0] = f2tf(qkv[(size_t)qrow * 3072 + c] * 0.125f);
        qa[ks][1] = f2tf(qkv[(size_t)(qrow + 8) * 3072 + c] * 0.125f);
        qa[ks][2] = f2tf(qkv[(size_t)qrow * 3072 + c + 4] * 0.125f);
        qa[ks][3] = f2tf(qkv[(size_t)(qrow + 8) * 3072 + c + 4] * 0.125f);
    }

    float m0 = -1e30f, m1 = -1e30f, l0 = 0.f, l1 = 0.f;
    float o[8][4];
#pragma unroll
    for (int nf = 0; nf < 8; nf++)
#pragma unroll
        for (int e = 0; e < 4; e++) o[nf][e] = 0.f;

    // K fill mapping (row-major): rows rr0 + p*16, cols dd..dd+3
    const int rr0 = tid >> 4;
    const int dd  = (tid & 15) * 4;
    // V fill mapping (transposed): d-row vd, kv cols vk0 + p*16 .. +3
    const int vd  = tid & 63;
    const int vk0 = (tid >> 6) * 4;
    const int pr  = warp * 16 + g;

    // LDSM lane-address components
    const int l8    = lane & 7;
    const int lhalf = (lane >> 3) & 1;   // +coladd(16B) for B-ops; +8 rows for A-ops
    const int lhi   = (lane >> 4) & 1;   // second matrix-pair selector

    const uint32_t skb  = s2u(sK);
    const uint32_t svtb = s2u(sVt);
    const uint32_t spb  = s2u(sP);

    // QK B-frags: pair nfp covers nf=2*nfp, 2*nfp+1 (rows n, cols k)
    uint32_t koff[8];
#pragma unroll
    for (int nfp = 0; nfp < 8; nfp++)
        koff[nfp] = (uint32_t)(((nfp * 2 + lhi) * 8 + l8) * 68 * 4) + lhalf * 16;
    // PV B-frags from sVt (rows d=n, cols kv=k)
    uint32_t voff[4];
#pragma unroll
    for (int nfp = 0; nfp < 4; nfp++)
        voff[nfp] = (uint32_t)(((nfp * 2 + lhi) * 8 + l8) * 132 * 4) + lhalf * 16;
    // PV A-frags from sP (warp-private 16 rows)
    const uint32_t paoff = (uint32_t)(((warp * 16 + l8 + lhalf * 8) * 132) * 4) + lhi * 16;

    for (int j = 0; j < 16; j++) {
        __syncthreads();
        const size_t kvbase = (size_t)(b * 2048 + j * 128) * 3072 + 1024 + (size_t)h * 64;
        // K: row-major fill
#pragma unroll
        for (int p = 0; p < 8; p++) {
            const int rr = rr0 + p * 16;
            const float4 kx = *reinterpret_cast<const float4*>(&qkv[kvbase + (size_t)rr * 3072 + dd]);
            float* dk = &sK[rr * 68 + dd];
            dk[0] = tf2f(kx.x); dk[1] = tf2f(kx.y); dk[2] = tf2f(kx.z); dk[3] = tf2f(kx.w);
        }
        // V: transposed fill sVt[d][kv]
#pragma unroll
        for (int p = 0; p < 8; p++) {
            const int kv0 = vk0 + p * 16;
            const size_t gb = kvbase + 1024 + (size_t)kv0 * 3072 + vd;
            float4 st = make_float4(tf2f(qkv[gb]),
                                    tf2f(qkv[gb + 3072]),
                                    tf2f(qkv[gb + 2 * 3072]),
                                    tf2f(qkv[gb + 3 * 3072]));
            *reinterpret_cast<float4*>(&sVt[vd * 132 + kv0]) = st;
        }
        __syncthreads();

        // S = Q @ K^T  (B-frags via LDSM)
        float s[16][4];
#pragma unroll
        for (int nf = 0; nf < 16; nf++)
#pragma unroll
            for (int e = 0; e < 4; e++) s[nf][e] = 0.f;
#pragma unroll
        for (int ks = 0; ks < 8; ks++) {
#pragma unroll
            for (int nfp = 0; nfp < 8; nfp++) {
                uint32_t bb[4];
                ldsm4(bb, skb + koff[nfp] + ks * 32);
                mma_tf32(s[nfp * 2],     qa[ks], bb[0], bb[1]);
                mma_tf32(s[nfp * 2 + 1], qa[ks], bb[2], bb[3]);
            }
        }

        // online softmax
        float rm0 = -1e30f, rm1 = -1e30f;
#pragma unroll
        for (int nf = 0; nf < 16; nf++) {
            rm0 = fmaxf(rm0, fmaxf(s[nf][0], s[nf][1]));
            rm1 = fmaxf(rm1, fmaxf(s[nf][2], s[nf][3]));
        }
        rm0 = fmaxf(rm0, __shfl_xor_sync(0xffffffffu, rm0, 1));
        rm0 = fmaxf(rm0, __shfl_xor_sync(0xffffffffu, rm0, 2));
        rm1 = fmaxf(rm1, __shfl_xor_sync(0xffffffffu, rm1, 1));
        rm1 = fmaxf(rm1, __shfl_xor_sync(0xffffffffu, rm1, 2));
        const float mn0 = fmaxf(m0, rm0), mn1 = fmaxf(m1, rm1);
        const float al0 = ex2f((m0 - mn0) * L2E), al1 = ex2f((m1 - mn1) * L2E);
        const float mb0 = mn0 * L2E, mb1 = mn1 * L2E;

        float rs0 = 0.f, rs1 = 0.f;
#pragma unroll
        for (int nf = 0; nf < 16; nf++) {
            const float p0 = tf2f(ex2f(fmaf(s[nf][0], L2E, -mb0)));
            const float p1 = tf2f(ex2f(fmaf(s[nf][1], L2E, -mb0)));
            const float p2 = tf2f(ex2f(fmaf(s[nf][2], L2E, -mb1)));
            const float p3 = tf2f(ex2f(fmaf(s[nf][3], L2E, -mb1)));
            rs0 += p0 + p1;
            rs1 += p2 + p3;
            *reinterpret_cast<float2*>(&sP[pr * 132 + nf * 8 + q * 2]) = make_float2(p0, p1);
            *reinterpret_cast<float2*>(&sP[(pr + 8) * 132 + nf * 8 + q * 2]) = make_float2(p2, p3);
        }
        rs0 += __shfl_xor_sync(0xffffffffu, rs0, 1);
        rs0 += __shfl_xor_sync(0xffffffffu, rs0, 2);
        rs1 += __shfl_xor_sync(0xffffffffu, rs1, 1);
        rs1 += __shfl_xor_sync(0xffffffffu, rs1, 2);
        l0 = l0 * al0 + rs0;
        l1 = l1 * al1 + rs1;
        m0 = mn0; m1 = mn1;
#pragma unroll
        for (int nf = 0; nf < 8; nf++) {
            o[nf][0] *= al0; o[nf][1] *= al0; o[nf][2] *= al1; o[nf][3] *= al1;
        }
        __syncwarp();  // sP stores visible within warp before LDSM reads

        // O += P @ V  (A and B frags via LDSM)
#pragma unroll
        for (int kb = 0; kb < 16; kb++) {
            uint32_t pa[4];
            ldsm4(pa, spb + paoff + kb * 32);
#pragma unroll
            for (int nfp = 0; nfp < 4; nfp++) {
                uint32_t vb[4];
                ldsm4(vb, svtb + voff[nfp] + kb * 32);
                mma_tf32(o[nfp * 2],     pa, vb[0], vb[1]);
                mma_tf32(o[nfp * 2 + 1], pa, vb[2], vb[3]);
            }
        }
    }

    const float il0 = 1.f / l0, il1 = 1.f / l1;
#pragma unroll
    for (int nf = 0; nf < 8; nf++) {
        const int c = h * 64 + nf * 8 + q * 2;
        *reinterpret_cast<float2*>(&attn[(size_t)qrow * 1024 + c]) =
            make_float2(o[nf][0] * il0, o[nf][1] * il0);
        *reinterpret_cast<float2*>(&attn[(size_t)(qrow + 8) * 1024 + c]) =
            make_float2(o[nf][2] * il1, o[nf][3] * il1);
    }
}

// ============================================================================
extern "C" void kernel_launch(void* const* d_in, const int* in_sizes, int n_in,
                              void* d_out, int out_size)
{
    const float* hidden = (const float*)d_in[0];
    const float* qkvw   = (const float*)d_in[1];
    const float* ow     = (const float*)d_in[2];
    const float* ssm    = (const float*)d_in[4];
    float* out = (float*)d_out;
    (void)in_sizes; (void)n_in; (void)out_size;

    const int smem_g = (2 * GM_SA + 2 * GM_SB) * 4;            // 71680 B
    const int smem_f = (FA_SK + FA_SVT + FA_SP) * 4;           // 136192 B
    cudaFuncSetAttribute(gemm_tf32, cudaFuncAttributeMaxDynamicSharedMemorySize, smem_g);
    cudaFuncSetAttribute(flash_tf32, cudaFuncAttributeMaxDynamicSharedMemorySize, smem_f);

    float *qkvp, *attnp;
    cudaGetSymbolAddress((void**)&qkvp, g_qkv);
    cudaGetSymbolAddress((void**)&attnp, g_attn);

    // QKV projection: [4096,1024] @ [1024,3072]
    gemm_tf32<<<dim3(3072 / 128, 4096 / 128), 256, smem_g>>>(
        hidden, qkvw, qkvp, 4096, 3072, 1024, nullptr);

    // attention: per (b, h, 128-row qtile)
    flash_tf32<<<dim3(16, 16, 2), 256, smem_f>>>(qkvp, attnp);

    // O projection with scaled_softmax folded in
    gemm_tf32<<<dim3(1024 / 128, 4096 / 128), 256, smem_g>>>(
        attnp, ow, out, 4096, 1024, 1024, ssm);
}